// round 10
// baseline (speedup 1.0000x reference)
#include <cuda_runtime.h>
#include <cuda_bf16.h>
#include <cstdint>

#define NN 2048
#define D  64
#define BI 16
#define BJ 16
#define NTILES  (128 * 128)
#define GRID    296

__device__ __align__(256) float g_A[NN * D];
__device__ __align__(256) float g_B[NN * D];

// ---------------- smem layout (bytes) ----------------
#define OFF_H1HI  0           // [256 rows][144B], warp-private by 32-row slice
#define OFF_H1LO  36864
#define OFF_W2HI  73728       // W2^T [64][72 bf16]
#define OFF_W2LO  82944
#define OFF_WOHI  92160       // Wout^T [16][72 bf16]
#define OFF_WOLO  94464
#define OFF_B2    96768       // 64 f32
#define OFF_BOUT  97024       // 16 f32
#define SMEM_BYTES 97088

__device__ __forceinline__ uint32_t smem_u32(const void* p) {
    uint32_t a;
    asm("{ .reg .u64 t; cvta.to.shared.u64 t, %1; cvt.u32.u64 %0, t; }" : "=r"(a) : "l"(p));
    return a;
}
__device__ __forceinline__ void ldsm_x4(uint32_t* r, uint32_t addr) {
    asm volatile("ldmatrix.sync.aligned.m8n8.x4.shared.b16 {%0,%1,%2,%3}, [%4];"
                 : "=r"(r[0]), "=r"(r[1]), "=r"(r[2]), "=r"(r[3]) : "r"(addr));
}
__device__ __forceinline__ void ldsm_x2(uint32_t* r, uint32_t addr) {
    asm volatile("ldmatrix.sync.aligned.m8n8.x2.shared.b16 {%0,%1}, [%2];"
                 : "=r"(r[0]), "=r"(r[1]) : "r"(addr));
}
__device__ __forceinline__ void mma_bf16(float* d, const uint32_t* a, const uint32_t* b) {
    asm volatile("mma.sync.aligned.m16n8k16.row.col.f32.bf16.bf16.f32 "
                 "{%0,%1,%2,%3}, {%4,%5,%6,%7}, {%8,%9}, {%0,%1,%2,%3};"
                 : "+f"(d[0]), "+f"(d[1]), "+f"(d[2]), "+f"(d[3])
                 : "r"(a[0]), "r"(a[1]), "r"(a[2]), "r"(a[3]), "r"(b[0]), "r"(b[1]));
}

union BU { __nv_bfloat162 b; uint32_t u; };
__device__ __forceinline__ uint32_t bsplit(float x, float y, uint32_t& lo) {
    BU h; h.b = __floats2bfloat162_rn(x, y);
    float rx = x - __bfloat162float(h.b.x);
    float ry = y - __bfloat162float(h.b.y);
    BU l; l.b = __floats2bfloat162_rn(rx, ry);
    lo = l.u;
    return h.u;
}
__device__ __forceinline__ bool tile_valid(int t) {
    return (t & 127) >= (t >> 7);      // bj >= bi
}

// ---------------------------------------------------------------------------
__global__ __launch_bounds__(128)
void k_pre(const float* __restrict__ X, const float* __restrict__ W1,
           const float* __restrict__ b1) {
    __shared__ float sx[D];
    const int i = blockIdx.x;
    const int t = threadIdx.x;
    if (t < D) sx[t] = X[i * D + t];
    __syncthreads();
    const int k = t & 63;
    const bool isA = t < 64;
    const float* w = W1 + (isA ? 0 : D * D) + k;
    float acc = isA ? b1[k] : 0.0f;
#pragma unroll
    for (int m = 0; m < D; m++) acc = fmaf(sx[m], w[m * D], acc);
    if (isA) g_A[i * D + k] = acc;
    else     g_B[i * D + k] = acc;
}

// ---------------------------------------------------------------------------
__global__ __launch_bounds__(256, 2)
void k_edge(const float* __restrict__ W2, const float* __restrict__ b2,
            const float* __restrict__ We, const float* __restrict__ be,
            const float* __restrict__ Wt, const float* __restrict__ bt,
            float* __restrict__ out) {
    extern __shared__ char smc[];
    const uint32_t sb = smem_u32(smc);
    const int tid  = threadIdx.x;
    const int wid  = tid >> 5;
    const int lane = tid & 31;

    __nv_bfloat16* w2hi = (__nv_bfloat16*)(smc + OFF_W2HI);
    __nv_bfloat16* w2lo = (__nv_bfloat16*)(smc + OFF_W2LO);
    __nv_bfloat16* wohi = (__nv_bfloat16*)(smc + OFF_WOHI);
    __nv_bfloat16* wolo = (__nv_bfloat16*)(smc + OFF_WOLO);
    float* sb2f = (float*)(smc + OFF_B2);
    float* sbof = (float*)(smc + OFF_BOUT);

    // ---- ONE-TIME: weights (transposed, bf16 hi/lo) + biases ----
    for (int idx = tid; idx < 4096; idx += 256) {
        int c = idx >> 6, k = idx & 63;
        float v = W2[k * 64 + c];
        __nv_bfloat16 hi = __float2bfloat16_rn(v);
        w2hi[c * 72 + k] = hi;
        w2lo[c * 72 + k] = __float2bfloat16_rn(v - __bfloat162float(hi));
    }
    for (int idx = tid; idx < 1024; idx += 256) {
        int o = idx >> 6, k = idx & 63;
        float v = (o == 0) ? We[k] : (o <= 8 ? Wt[k * 8 + (o - 1)] : 0.0f);
        __nv_bfloat16 hi = __float2bfloat16_rn(v);
        wohi[o * 72 + k] = hi;
        wolo[o * 72 + k] = __float2bfloat16_rn(v - __bfloat162float(hi));
    }
    if (tid < 64) sb2f[tid] = b2[tid];
    if (tid < 16) sbof[tid] = (tid == 0) ? be[0] : (tid <= 8 ? bt[tid - 1] : 0.0f);
    __syncthreads();   // the ONLY CTA-wide barrier

    const int m0 = wid * 32;                    // warp's 32 rows (= its own tids)
    const int Lb = lane & 15;
    const uint32_t aBase = sb + (uint32_t)((m0 + (lane & 15)) * 144 + (lane >> 4) * 16);
    const uint32_t bBase = sb + (uint32_t)((Lb & 7) * 144 + (Lb >> 3) * 16);
    const int g  = lane >> 2;
    const int cw = 2 * (lane & 3);

    // phase-1 mapping: row = tid (warp-private 32-row slice)
    const int p1li = tid >> 4, p1lj = tid & 15;
    const int rot  = (tid >> 3) & 7;

    for (int t = blockIdx.x; t < NTILES; t += GRID) {
        if (!tile_valid(t)) continue;
        const int i0 = (t >> 7) * BI, j0 = (t & 127) * BJ;

        __syncwarp();   // prior head ldsm of this warp's rows fully drained

        // ---- phase 1: H1 = relu(A+B) -> hi/lo bf16; direct LDG ----
        {
            const float4* pa = (const float4*)(g_A + (i0 + p1li) * D);
            const float4* pb = (const float4*)(g_B + (j0 + p1lj) * D);
#pragma unroll
            for (int k8i = 0; k8i < 8; k8i++) {
                int k8 = (k8i + rot) & 7;
                float4 a0 = __ldg(pa + 2 * k8);
                float4 a1 = __ldg(pa + 2 * k8 + 1);
                float4 b0 = __ldg(pb + 2 * k8);
                float4 b1 = __ldg(pb + 2 * k8 + 1);
                float h[8] = {fmaxf(a0.x + b0.x, 0.f), fmaxf(a0.y + b0.y, 0.f),
                              fmaxf(a0.z + b0.z, 0.f), fmaxf(a0.w + b0.w, 0.f),
                              fmaxf(a1.x + b1.x, 0.f), fmaxf(a1.y + b1.y, 0.f),
                              fmaxf(a1.z + b1.z, 0.f), fmaxf(a1.w + b1.w, 0.f)};
                uint32_t hi[4], lo[4];
#pragma unroll
                for (int v = 0; v < 4; v++) hi[v] = bsplit(h[2 * v], h[2 * v + 1], lo[v]);
                *(uint4*)(smc + OFF_H1HI + tid * 144 + k8 * 16) = make_uint4(hi[0], hi[1], hi[2], hi[3]);
                *(uint4*)(smc + OFF_H1LO + tid * 144 + k8 * 16) = make_uint4(lo[0], lo[1], lo[2], lo[3]);
            }
        }
        __syncwarp();

        // ---- main GEMM: warp = 32 rows x 64 cols ----
        float acc[2][8][4];
#pragma unroll
        for (int mb = 0; mb < 2; mb++)
#pragma unroll
            for (int nb = 0; nb < 8; nb++) {
                float v0 = sb2f[8 * nb + cw], v1 = sb2f[8 * nb + cw + 1];
                acc[mb][nb][0] = v0; acc[mb][nb][1] = v1;
                acc[mb][nb][2] = v0; acc[mb][nb][3] = v1;
            }
#pragma unroll
        for (int kb = 0; kb < 4; kb++) {
            uint32_t ahi[2][4], alo[2][4];
#pragma unroll
            for (int mb = 0; mb < 2; mb++) {
                uint32_t aa = aBase + mb * 16 * 144 + kb * 32;
                ldsm_x4(ahi[mb], aa + OFF_H1HI);
                ldsm_x4(alo[mb], aa + OFF_H1LO);
            }
#pragma unroll
            for (int nh = 0; nh < 2; nh++) {
                uint32_t bh[4][2], bl[4][2];
#pragma unroll
                for (int q = 0; q < 4; q++) {
                    int nb = nh * 4 + q;
                    ldsm_x2(bh[q], bBase + OFF_W2HI + nb * 8 * 144 + kb * 32);
                    ldsm_x2(bl[q], bBase + OFF_W2LO + nb * 8 * 144 + kb * 32);
                }
#pragma unroll
                for (int mb = 0; mb < 2; mb++)
#pragma unroll
                    for (int q = 0; q < 4; q++) {
                        mma_bf16(acc[mb][nh * 4 + q], ahi[mb], bh[q]);
                        mma_bf16(acc[mb][nh * 4 + q], ahi[mb], bl[q]);
                        mma_bf16(acc[mb][nh * 4 + q], alo[mb], bh[q]);
                    }
            }
        }
        __syncwarp();   // warp's own H1 reads done before overwrite

        // ---- epilogue: relu + split -> H2 (warp-private rows) ----
#pragma unroll
        for (int mb = 0; mb < 2; mb++) {
            int r0 = m0 + 16 * mb + g;
#pragma unroll
            for (int nb = 0; nb < 8; nb++) {
                int cb = (8 * nb + cw) * 2;
                uint32_t l0, l1;
                uint32_t h0 = bsplit(fmaxf(acc[mb][nb][0], 0.f), fmaxf(acc[mb][nb][1], 0.f), l0);
                uint32_t h1 = bsplit(fmaxf(acc[mb][nb][2], 0.f), fmaxf(acc[mb][nb][3], 0.f), l1);
                *(uint32_t*)(smc + OFF_H1HI + r0 * 144 + cb)       = h0;
                *(uint32_t*)(smc + OFF_H1LO + r0 * 144 + cb)       = l0;
                *(uint32_t*)(smc + OFF_H1HI + (r0 + 8) * 144 + cb) = h1;
                *(uint32_t*)(smc + OFF_H1LO + (r0 + 8) * 144 + cb) = l1;
            }
        }
        __syncwarp();

        // ---- head GEMM: warp = 32 rows x 16 cols, then triu store ----
        {
            float hacc[2][2][4];
#pragma unroll
            for (int mb = 0; mb < 2; mb++)
#pragma unroll
                for (int nb = 0; nb < 2; nb++) {
                    float v0 = sbof[8 * nb + cw], v1 = sbof[8 * nb + cw + 1];
                    hacc[mb][nb][0] = v0; hacc[mb][nb][1] = v1;
                    hacc[mb][nb][2] = v0; hacc[mb][nb][3] = v1;
                }
#pragma unroll
            for (int kb = 0; kb < 4; kb++) {
                uint32_t bh2[2][2], bl2[2][2];
#pragma unroll
                for (int nb = 0; nb < 2; nb++) {
                    ldsm_x2(bh2[nb], bBase + OFF_WOHI + nb * 8 * 144 + kb * 32);
                    ldsm_x2(bl2[nb], bBase + OFF_WOLO + nb * 8 * 144 + kb * 32);
                }
#pragma unroll
                for (int mb = 0; mb < 2; mb++) {
                    uint32_t ahi[4], alo[4];
                    uint32_t aa = aBase + mb * 16 * 144 + kb * 32;
                    ldsm_x4(ahi, aa + OFF_H1HI);
                    ldsm_x4(alo, aa + OFF_H1LO);
#pragma unroll
                    for (int nb = 0; nb < 2; nb++) {
                        mma_bf16(hacc[mb][nb], ahi, bh2[nb]);
                        mma_bf16(hacc[mb][nb], ahi, bl2[nb]);
                        mma_bf16(hacc[mb][nb], alo, bh2[nb]);
                    }
                }
            }
#pragma unroll
            for (int mb = 0; mb < 2; mb++)
#pragma unroll
                for (int half = 0; half < 2; half++) {
                    int r = m0 + 16 * mb + g + 8 * half;
                    int li = r >> 4, lj = r & 15;
                    int i = i0 + li, j = j0 + lj;
                    if (j > i) {
                        long p = (long)i * (2 * NN - i - 1) / 2 + (j - i - 1);
                        float* po = out + p * 9;
#pragma unroll
                        for (int nb = 0; nb < 2; nb++) {
                            int c0 = 8 * nb + cw;
                            if (c0 < 9)     po[c0]     = hacc[nb == 0 ? mb : mb][nb][2 * half];
                            if (c0 + 1 < 9) po[c0 + 1] = hacc[mb][nb][2 * half + 1];
                        }
                    }
                }
        }
    }
}

// ---------------------------------------------------------------------------
extern "C" void kernel_launch(void* const* d_in, const int* in_sizes, int n_in,
                              void* d_out, int out_size) {
    const float* X  = (const float*)d_in[0];
    const float* W1 = (const float*)d_in[1];
    const float* b1 = (const float*)d_in[2];
    const float* W2 = (const float*)d_in[3];
    const float* b2 = (const float*)d_in[4];
    const float* We = (const float*)d_in[5];
    const float* be = (const float*)d_in[6];
    const float* Wt = (const float*)d_in[7];
    const float* bt = (const float*)d_in[8];
    float* out = (float*)d_out;

    cudaFuncSetAttribute(k_edge, cudaFuncAttributeMaxDynamicSharedMemorySize, SMEM_BYTES);

    k_pre<<<NN, 128>>>(X, W1, b1);
    k_edge<<<GRID, 256, SMEM_BYTES>>>(W2, b2, We, be, Wt, bt, out);
}